// round 2
// baseline (speedup 1.0000x reference)
#include <cuda_runtime.h>
#include <math.h>

#define N_NODES   100000
#define N_EDGES   1000000
#define HID       64
#define OUT_DIM   32
#define NUM_GRAPHS 512

// ---------------- device scratch (static: no allocations allowed) ----------
__device__ float g_agg[N_NODES * HID];          // x + sum_{j->i} x_j  (per layer)
__device__ float g_h[N_NODES * HID];            // post-ReLU layer-0 output
__device__ float g_sums[NUM_GRAPHS * HID];      // pooled sums
__device__ float g_Wc[HID * OUT_DIM];           // fused Wp1@Wp2
__device__ float g_bc[OUT_DIM];                 // fused bp1@Wp2 + bp2
__device__ int   g_is64;                        // dtype flag for indices
__device__ int   g_ei[2 * N_EDGES];             // repacked edge_index (int32)
__device__ int   g_batch[N_NODES];              // repacked batch (int32)

// ---------------- dtype probe + repack --------------------------------------
// If edge_index is int64 (values < 2^31, little-endian), every odd int32 word
// of the buffer is 0. If it is int32, odd words are random node indices.
__global__ void k_detect(const int* __restrict__ ei32) {
    __shared__ int nz;
    if (threadIdx.x == 0) nz = 0;
    __syncthreads();
    if (ei32[2 * threadIdx.x + 1] != 0) nz = 1;   // benign race
    __syncthreads();
    if (threadIdx.x == 0) g_is64 = (nz == 0) ? 1 : 0;
}

__global__ void k_repack_ei(const void* __restrict__ eiv) {
    int i = blockIdx.x * blockDim.x + threadIdx.x;
    if (i >= 2 * N_EDGES) return;
    g_ei[i] = g_is64 ? (int)((const long long*)eiv)[i]
                     : ((const int*)eiv)[i];
}

__global__ void k_repack_batch(const void* __restrict__ bv) {
    int i = blockIdx.x * blockDim.x + threadIdx.x;
    if (i >= N_NODES) return;
    g_batch[i] = g_is64 ? (int)((const long long*)bv)[i]
                        : ((const int*)bv)[i];
}

// ---------------- tiny utility kernels -------------------------------------
__global__ void k_zero_sums() {
    int i = blockIdx.x * blockDim.x + threadIdx.x;
    if (i < NUM_GRAPHS * HID) g_sums[i] = 0.0f;
}

__global__ void k_copy_x_to_agg(const float4* __restrict__ src) {
    int i = blockIdx.x * blockDim.x + threadIdx.x;
    const int n4 = N_NODES * HID / 4;
    if (i < n4) reinterpret_cast<float4*>(g_agg)[i] = src[i];
}

// fuse head weights: Wc[k][c] = sum_m Wp1[k][m]*Wp2[m][c]; bc = bp1@Wp2 + bp2
__global__ void k_fuse_head(const float* __restrict__ Wp1, const float* __restrict__ bp1,
                            const float* __restrict__ Wp2, const float* __restrict__ bp2) {
    int i = blockIdx.x * blockDim.x + threadIdx.x;
    if (i < HID * OUT_DIM) {
        int k = i >> 5, c = i & 31;
        float s = 0.0f;
        for (int m = 0; m < HID; m++) s += Wp1[k * HID + m] * Wp2[m * OUT_DIM + c];
        g_Wc[i] = s;
    } else if (i < HID * OUT_DIM + OUT_DIM) {
        int c = i - HID * OUT_DIM;
        float s = bp2[c];
        for (int m = 0; m < HID; m++) s += bp1[m] * Wp2[m * OUT_DIM + c];
        g_bc[c] = s;
    }
}

// ---------------- edge scatter: agg[dst] += src_feat[src] ------------------
// 16 threads per edge, float4 each. USE_H selects layer-1 input (g_h).
template <bool USE_H>
__global__ void k_scatter(const float* __restrict__ x) {
    int idx = blockIdx.x * blockDim.x + threadIdx.x;
    if (idx >= N_EDGES * 16) return;
    int e = idx >> 4;
    int c = idx & 15;
    const float* src_feat = USE_H ? g_h : x;
    int s = g_ei[e];
    int d = g_ei[N_EDGES + e];
    float4 v = __ldg(reinterpret_cast<const float4*>(src_feat + (size_t)s * HID) + c);
    float* out = g_agg + (size_t)d * HID + c * 4;
    atomicAdd(out + 0, v.x);
    atomicAdd(out + 1, v.y);
    atomicAdd(out + 2, v.z);
    atomicAdd(out + 3, v.w);
}

// ---------------- fused GIN MLP: out = relu(in@W1+b1)@W2+b2 ----------------
// MODE 0: write relu(result) to BOTH g_h and g_agg (next layer input + self term)
// MODE 1: write raw result (emb) to emb_out
// Input is always g_agg. One thread per node, 64 fp32 accumulators.
template <int MODE>
__global__ void __launch_bounds__(128) k_mlp(
    const float* __restrict__ W1, const float* __restrict__ b1,
    const float* __restrict__ W2, const float* __restrict__ b2,
    float* __restrict__ emb_out) {
    __shared__ float sh[128 * 65];   // padded rows -> conflict-free per-thread access
    const int t = threadIdx.x;
    const int base = blockIdx.x * 128;

    // stage 128 input rows, globally coalesced
    #pragma unroll
    for (int it = 0; it < 16; it++) {
        int L4 = t + 128 * it;           // float4 index within tile
        int row = L4 >> 4, c4 = L4 & 15;
        int node = base + row;
        float4 v = make_float4(0.f, 0.f, 0.f, 0.f);
        if (node < N_NODES)
            v = __ldg(reinterpret_cast<const float4*>(g_agg + (size_t)node * HID) + c4);
        float* p = sh + row * 65 + c4 * 4;
        p[0] = v.x; p[1] = v.y; p[2] = v.z; p[3] = v.w;
    }
    __syncthreads();

    const int node = base + t;
    float* myrow = sh + t * 65;
    float acc[HID];

    // phase 1: acc = in @ W1 + b1
    const float4* b1v = reinterpret_cast<const float4*>(b1);
    #pragma unroll
    for (int j4 = 0; j4 < 16; j4++) {
        float4 bb = __ldg(b1v + j4);
        acc[4 * j4 + 0] = bb.x; acc[4 * j4 + 1] = bb.y;
        acc[4 * j4 + 2] = bb.z; acc[4 * j4 + 3] = bb.w;
    }
    const float4* W1v = reinterpret_cast<const float4*>(W1);
    for (int k = 0; k < HID; k++) {
        float ik = myrow[k];
        #pragma unroll
        for (int j4 = 0; j4 < 16; j4++) {
            float4 w = __ldg(W1v + k * 16 + j4);
            acc[4 * j4 + 0] += ik * w.x;
            acc[4 * j4 + 1] += ik * w.y;
            acc[4 * j4 + 2] += ik * w.z;
            acc[4 * j4 + 3] += ik * w.w;
        }
    }
    // relu(acc) -> my shared row (own row only; no sync needed)
    #pragma unroll
    for (int j = 0; j < HID; j++) myrow[j] = fmaxf(acc[j], 0.0f);

    // phase 2: acc = relu(...) @ W2 + b2
    const float4* b2v = reinterpret_cast<const float4*>(b2);
    #pragma unroll
    for (int j4 = 0; j4 < 16; j4++) {
        float4 bb = __ldg(b2v + j4);
        acc[4 * j4 + 0] = bb.x; acc[4 * j4 + 1] = bb.y;
        acc[4 * j4 + 2] = bb.z; acc[4 * j4 + 3] = bb.w;
    }
    const float4* W2v = reinterpret_cast<const float4*>(W2);
    for (int k = 0; k < HID; k++) {
        float ik = myrow[k];
        #pragma unroll
        for (int j4 = 0; j4 < 16; j4++) {
            float4 w = __ldg(W2v + k * 16 + j4);
            acc[4 * j4 + 0] += ik * w.x;
            acc[4 * j4 + 1] += ik * w.y;
            acc[4 * j4 + 2] += ik * w.z;
            acc[4 * j4 + 3] += ik * w.w;
        }
    }

    if (node >= N_NODES) return;

    if (MODE == 0) {
        float* h = g_h + (size_t)node * HID;
        float* a = g_agg + (size_t)node * HID;
        #pragma unroll
        for (int j4 = 0; j4 < 16; j4++) {
            float4 r;
            r.x = fmaxf(acc[4 * j4 + 0], 0.f);
            r.y = fmaxf(acc[4 * j4 + 1], 0.f);
            r.z = fmaxf(acc[4 * j4 + 2], 0.f);
            r.w = fmaxf(acc[4 * j4 + 3], 0.f);
            reinterpret_cast<float4*>(h)[j4] = r;
            reinterpret_cast<float4*>(a)[j4] = r;
        }
    } else {
        float* o = emb_out + (size_t)node * HID;
        #pragma unroll
        for (int j4 = 0; j4 < 16; j4++) {
            float4 r;
            r.x = acc[4 * j4 + 0]; r.y = acc[4 * j4 + 1];
            r.z = acc[4 * j4 + 2]; r.w = acc[4 * j4 + 3];
            reinterpret_cast<float4*>(o)[j4] = r;
        }
    }
}

// ---------------- pooling: sums[batch[n]] += relu(emb[n]) ------------------
__global__ void k_pool(const float* __restrict__ emb) {
    int idx = blockIdx.x * blockDim.x + threadIdx.x;
    if (idx >= N_NODES * 16) return;
    int node = idx >> 4;
    int c = idx & 15;
    int g = g_batch[node];
    float4 v = __ldg(reinterpret_cast<const float4*>(emb + (size_t)node * HID) + c);
    float* s = g_sums + (size_t)g * HID + c * 4;
    atomicAdd(s + 0, fmaxf(v.x, 0.f));
    atomicAdd(s + 1, fmaxf(v.y, 0.f));
    atomicAdd(s + 2, fmaxf(v.z, 0.f));
    atomicAdd(s + 3, fmaxf(v.w, 0.f));
}

// ---------------- final head: pooled @ Wc + bc, log_softmax ----------------
__global__ void k_final(float* __restrict__ outp) {
    int g = blockIdx.x * blockDim.x + threadIdx.x;
    if (g >= NUM_GRAPHS) return;
    // counts via binary search on sorted batch
    int l0, l1;
    {
        int v = g;
        int a = 0, b = N_NODES;
        while (a < b) { int m = (a + b) >> 1; if (g_batch[m] < v) a = m + 1; else b = m; }
        l0 = a;
        v = g + 1; a = l0; b = N_NODES;
        while (a < b) { int m = (a + b) >> 1; if (g_batch[m] < v) a = m + 1; else b = m; }
        l1 = a;
    }
    float cnt = (float)(l1 - l0);
    float inv = 1.0f / fmaxf(cnt, 1.0f);

    float acc[OUT_DIM];
    #pragma unroll
    for (int c = 0; c < OUT_DIM; c++) acc[c] = g_bc[c];
    for (int k = 0; k < HID; k++) {
        float p = g_sums[g * HID + k] * inv;
        #pragma unroll
        for (int c = 0; c < OUT_DIM; c++) acc[c] += p * g_Wc[k * OUT_DIM + c];
    }
    float m = acc[0];
    #pragma unroll
    for (int c = 1; c < OUT_DIM; c++) m = fmaxf(m, acc[c]);
    float s = 0.0f;
    #pragma unroll
    for (int c = 0; c < OUT_DIM; c++) s += expf(acc[c] - m);
    float ls = logf(s) + m;
    #pragma unroll
    for (int c = 0; c < OUT_DIM; c++) outp[g * OUT_DIM + c] = acc[c] - ls;
}

// ---------------- host launch ----------------------------------------------
extern "C" void kernel_launch(void* const* d_in, const int* in_sizes, int n_in,
                              void* d_out, int out_size) {
    const float* x     = (const float*)d_in[0];
    const void*  ei    = d_in[1];
    const void*  batch = d_in[2];
    const float* W1a = (const float*)d_in[3];
    const float* b1a = (const float*)d_in[4];
    const float* W2a = (const float*)d_in[5];
    const float* b2a = (const float*)d_in[6];
    const float* W1b = (const float*)d_in[7];
    const float* b1b = (const float*)d_in[8];
    const float* W2b = (const float*)d_in[9];
    const float* b2b = (const float*)d_in[10];
    const float* Wp1 = (const float*)d_in[11];
    const float* bp1 = (const float*)d_in[12];
    const float* Wp2 = (const float*)d_in[13];
    const float* bp2 = (const float*)d_in[14];

    float* out     = (float*)d_out;
    float* emb_out = out;                                  // [N_NODES, HID]
    float* lsm_out = out + (size_t)N_NODES * HID;          // [NUM_GRAPHS, OUT_DIM]

    const int mlp_blocks     = (N_NODES + 127) / 128;
    const int copy_blocks    = (N_NODES * HID / 4 + 255) / 256;
    const int scatter_blocks = (N_EDGES * 16 + 255) / 256;
    const int pool_blocks    = (N_NODES * 16 + 255) / 256;

    // dtype probe + repack indices to int32
    k_detect<<<1, 256>>>((const int*)ei);
    k_repack_ei<<<(2 * N_EDGES + 255) / 256, 256>>>(ei);
    k_repack_batch<<<(N_NODES + 255) / 256, 256>>>(batch);

    k_zero_sums<<<(NUM_GRAPHS * HID + 511) / 512, 512>>>();
    k_fuse_head<<<9, 256>>>(Wp1, bp1, Wp2, bp2);

    // layer 0
    k_copy_x_to_agg<<<copy_blocks, 256>>>(reinterpret_cast<const float4*>(x));
    k_scatter<false><<<scatter_blocks, 256>>>(x);
    k_mlp<0><<<mlp_blocks, 128>>>(W1a, b1a, W2a, b2a, nullptr);

    // layer 1 (g_agg already seeded with relu(h0) by k_mlp<0>)
    k_scatter<true><<<scatter_blocks, 256>>>(x);
    k_mlp<1><<<mlp_blocks, 128>>>(W1b, b1b, W2b, b2b, emb_out);

    // pooling + head
    k_pool<<<pool_blocks, 256>>>(emb_out);
    k_final<<<(NUM_GRAPHS + 127) / 128, 128>>>(lsm_out);
}

// round 3
// speedup vs baseline: 2.6938x; 2.6938x over previous
#include <cuda_runtime.h>
#include <math.h>

#define N_NODES   100000
#define N_EDGES   1000000
#define HID       64
#define OUT_DIM   32
#define NUM_GRAPHS 512

// ---------------- device scratch (static: no allocations allowed) ----------
__device__ float g_agg[N_NODES * HID];          // x + sum_{j->i} x_j  (per layer)
__device__ float g_h[N_NODES * HID];            // post-ReLU layer-0 output
__device__ float g_sums[NUM_GRAPHS * HID];      // pooled sums
__device__ float g_Wc[HID * OUT_DIM];           // fused Wp1@Wp2
__device__ float g_bc[OUT_DIM];                 // fused bp1@Wp2 + bp2
__device__ int   g_is64;                        // dtype flag for indices
__device__ int   g_ei[2 * N_EDGES];             // repacked edge_index (int32)
__device__ int   g_batch[N_NODES];              // repacked batch (int32)

// ---------------- vectorized global reduction -------------------------------
__device__ __forceinline__ void red_add_v4(float* addr, float a, float b, float c, float d) {
    asm volatile("red.global.add.v4.f32 [%0], {%1,%2,%3,%4};"
                 :: "l"(addr), "f"(a), "f"(b), "f"(c), "f"(d) : "memory");
}

// ---------------- dtype probe + repack --------------------------------------
__global__ void k_detect(const int* __restrict__ ei32) {
    __shared__ int nz;
    if (threadIdx.x == 0) nz = 0;
    __syncthreads();
    if (ei32[2 * threadIdx.x + 1] != 0) nz = 1;   // benign race
    __syncthreads();
    if (threadIdx.x == 0) g_is64 = (nz == 0) ? 1 : 0;
}

__global__ void k_repack_ei(const void* __restrict__ eiv) {
    int i = blockIdx.x * blockDim.x + threadIdx.x;
    if (i >= 2 * N_EDGES) return;
    g_ei[i] = g_is64 ? (int)((const long long*)eiv)[i]
                     : ((const int*)eiv)[i];
}

__global__ void k_repack_batch(const void* __restrict__ bv) {
    int i = blockIdx.x * blockDim.x + threadIdx.x;
    if (i >= N_NODES) return;
    g_batch[i] = g_is64 ? (int)((const long long*)bv)[i]
                        : ((const int*)bv)[i];
}

// ---------------- tiny utility kernels -------------------------------------
__global__ void k_zero_sums() {
    int i = blockIdx.x * blockDim.x + threadIdx.x;
    if (i < NUM_GRAPHS * HID) g_sums[i] = 0.0f;
}

__global__ void k_copy_x_to_agg(const float4* __restrict__ src) {
    int i = blockIdx.x * blockDim.x + threadIdx.x;
    const int n4 = N_NODES * HID / 4;
    if (i < n4) reinterpret_cast<float4*>(g_agg)[i] = src[i];
}

// fuse head weights: Wc = Wp1@Wp2 ; bc = bp1@Wp2 + bp2
__global__ void k_fuse_head(const float* __restrict__ Wp1, const float* __restrict__ bp1,
                            const float* __restrict__ Wp2, const float* __restrict__ bp2) {
    int i = blockIdx.x * blockDim.x + threadIdx.x;
    if (i < HID * OUT_DIM) {
        int k = i >> 5, c = i & 31;
        float s = 0.0f;
        for (int m = 0; m < HID; m++) s += Wp1[k * HID + m] * Wp2[m * OUT_DIM + c];
        g_Wc[i] = s;
    } else if (i < HID * OUT_DIM + OUT_DIM) {
        int c = i - HID * OUT_DIM;
        float s = bp2[c];
        for (int m = 0; m < HID; m++) s += bp1[m] * Wp2[m * OUT_DIM + c];
        g_bc[c] = s;
    }
}

// ---------------- edge scatter: agg[dst] += src_feat[src] ------------------
// 16 threads per edge, one red.v4 each. USE_H selects layer-1 input (g_h).
template <bool USE_H>
__global__ void k_scatter(const float* __restrict__ x) {
    int idx = blockIdx.x * blockDim.x + threadIdx.x;
    if (idx >= N_EDGES * 16) return;
    int e = idx >> 4;
    int c = idx & 15;
    const float* src_feat = USE_H ? g_h : x;
    int s = g_ei[e];
    int d = g_ei[N_EDGES + e];
    float4 v = __ldg(reinterpret_cast<const float4*>(src_feat + (size_t)s * HID) + c);
    float* out = g_agg + (size_t)d * HID + c * 4;
    red_add_v4(out, v.x, v.y, v.z, v.w);
}

// ---------------- fused GIN MLP: out = relu(in@W1+b1)@W2+b2 ----------------
// Block of 128 threads computes a 64-node x 64-col tile.
// Thread layout: cg = tid&15 (4 output cols), ng = tid>>4 (8 node rows).
// MODE 0: write relu(result) to g_h AND g_agg (next layer input + self term)
// MODE 1: write raw result (emb) to emb_out, and red relu(result) into g_sums
template <int MODE>
__global__ void __launch_bounds__(128) k_mlp(
    const float* __restrict__ W1, const float* __restrict__ b1,
    const float* __restrict__ W2, const float* __restrict__ b2,
    float* __restrict__ emb_out) {
    __shared__ float A[64 * 65];
    __shared__ float Hs[64 * 65];
    const int t = threadIdx.x;
    const int base = blockIdx.x * 64;
    const int cg = t & 15;
    const int ng = t >> 4;

    // stage 64 input rows (coalesced)
    #pragma unroll
    for (int it = 0; it < 8; it++) {
        int L4 = t + 128 * it;
        int row = L4 >> 4, c4 = L4 & 15;
        int node = base + row;
        float4 v = make_float4(0.f, 0.f, 0.f, 0.f);
        if (node < N_NODES)
            v = __ldg(reinterpret_cast<const float4*>(g_agg + (size_t)node * HID) + c4);
        float* p = A + row * 65 + c4 * 4;
        p[0] = v.x; p[1] = v.y; p[2] = v.z; p[3] = v.w;
    }
    __syncthreads();

    float acc[8][4];

    // ---- phase 1: A @ W1 + b1, relu -> Hs ----
    {
        float4 bb = __ldg(reinterpret_cast<const float4*>(b1) + cg);
        #pragma unroll
        for (int r = 0; r < 8; r++) {
            acc[r][0] = bb.x; acc[r][1] = bb.y; acc[r][2] = bb.z; acc[r][3] = bb.w;
        }
        const float4* Wv = reinterpret_cast<const float4*>(W1);
        #pragma unroll 4
        for (int k = 0; k < HID; k++) {
            float4 w = __ldg(Wv + k * 16 + cg);
            #pragma unroll
            for (int r = 0; r < 8; r++) {
                float a = A[(ng * 8 + r) * 65 + k];
                acc[r][0] += a * w.x; acc[r][1] += a * w.y;
                acc[r][2] += a * w.z; acc[r][3] += a * w.w;
            }
        }
        #pragma unroll
        for (int r = 0; r < 8; r++) {
            float* p = Hs + (ng * 8 + r) * 65 + cg * 4;
            p[0] = fmaxf(acc[r][0], 0.f); p[1] = fmaxf(acc[r][1], 0.f);
            p[2] = fmaxf(acc[r][2], 0.f); p[3] = fmaxf(acc[r][3], 0.f);
        }
    }
    __syncthreads();

    // ---- phase 2: Hs @ W2 + b2 ----
    {
        float4 bb = __ldg(reinterpret_cast<const float4*>(b2) + cg);
        #pragma unroll
        for (int r = 0; r < 8; r++) {
            acc[r][0] = bb.x; acc[r][1] = bb.y; acc[r][2] = bb.z; acc[r][3] = bb.w;
        }
        const float4* Wv = reinterpret_cast<const float4*>(W2);
        #pragma unroll 4
        for (int k = 0; k < HID; k++) {
            float4 w = __ldg(Wv + k * 16 + cg);
            #pragma unroll
            for (int r = 0; r < 8; r++) {
                float a = Hs[(ng * 8 + r) * 65 + k];
                acc[r][0] += a * w.x; acc[r][1] += a * w.y;
                acc[r][2] += a * w.z; acc[r][3] += a * w.w;
            }
        }
    }

    // ---- epilogue ----
    #pragma unroll
    for (int r = 0; r < 8; r++) {
        int node = base + ng * 8 + r;
        if (node >= N_NODES) continue;
        if (MODE == 0) {
            float4 rv;
            rv.x = fmaxf(acc[r][0], 0.f); rv.y = fmaxf(acc[r][1], 0.f);
            rv.z = fmaxf(acc[r][2], 0.f); rv.w = fmaxf(acc[r][3], 0.f);
            *reinterpret_cast<float4*>(g_h   + (size_t)node * HID + cg * 4) = rv;
            *reinterpret_cast<float4*>(g_agg + (size_t)node * HID + cg * 4) = rv;
        } else {
            float4 rv;
            rv.x = acc[r][0]; rv.y = acc[r][1]; rv.z = acc[r][2]; rv.w = acc[r][3];
            *reinterpret_cast<float4*>(emb_out + (size_t)node * HID + cg * 4) = rv;
            int gidx = g_batch[node];
            red_add_v4(g_sums + (size_t)gidx * HID + cg * 4,
                       fmaxf(rv.x, 0.f), fmaxf(rv.y, 0.f),
                       fmaxf(rv.z, 0.f), fmaxf(rv.w, 0.f));
        }
    }
}

// ---------------- final head: pooled @ Wc + bc, log_softmax ----------------
__global__ void k_final(float* __restrict__ outp) {
    int g = blockIdx.x * blockDim.x + threadIdx.x;
    if (g >= NUM_GRAPHS) return;
    int l0, l1;
    {
        int v = g;
        int a = 0, b = N_NODES;
        while (a < b) { int m = (a + b) >> 1; if (g_batch[m] < v) a = m + 1; else b = m; }
        l0 = a;
        v = g + 1; a = l0; b = N_NODES;
        while (a < b) { int m = (a + b) >> 1; if (g_batch[m] < v) a = m + 1; else b = m; }
        l1 = a;
    }
    float cnt = (float)(l1 - l0);
    float inv = 1.0f / fmaxf(cnt, 1.0f);

    float acc[OUT_DIM];
    #pragma unroll
    for (int c = 0; c < OUT_DIM; c++) acc[c] = g_bc[c];
    for (int k = 0; k < HID; k++) {
        float p = g_sums[g * HID + k] * inv;
        #pragma unroll
        for (int c = 0; c < OUT_DIM; c++) acc[c] += p * g_Wc[k * OUT_DIM + c];
    }
    float m = acc[0];
    #pragma unroll
    for (int c = 1; c < OUT_DIM; c++) m = fmaxf(m, acc[c]);
    float s = 0.0f;
    #pragma unroll
    for (int c = 0; c < OUT_DIM; c++) s += expf(acc[c] - m);
    float ls = logf(s) + m;
    #pragma unroll
    for (int c = 0; c < OUT_DIM; c++) outp[g * OUT_DIM + c] = acc[c] - ls;
}

// ---------------- host launch ----------------------------------------------
extern "C" void kernel_launch(void* const* d_in, const int* in_sizes, int n_in,
                              void* d_out, int out_size) {
    const float* x     = (const float*)d_in[0];
    const void*  ei    = d_in[1];
    const void*  batch = d_in[2];
    const float* W1a = (const float*)d_in[3];
    const float* b1a = (const float*)d_in[4];
    const float* W2a = (const float*)d_in[5];
    const float* b2a = (const float*)d_in[6];
    const float* W1b = (const float*)d_in[7];
    const float* b1b = (const float*)d_in[8];
    const float* W2b = (const float*)d_in[9];
    const float* b2b = (const float*)d_in[10];
    const float* Wp1 = (const float*)d_in[11];
    const float* bp1 = (const float*)d_in[12];
    const float* Wp2 = (const float*)d_in[13];
    const float* bp2 = (const float*)d_in[14];

    float* out     = (float*)d_out;
    float* emb_out = out;                                  // [N_NODES, HID]
    float* lsm_out = out + (size_t)N_NODES * HID;          // [NUM_GRAPHS, OUT_DIM]

    const int mlp_blocks     = (N_NODES + 63) / 64;
    const int copy_blocks    = (N_NODES * HID / 4 + 255) / 256;
    const int scatter_blocks = (N_EDGES * 16 + 255) / 256;

    // dtype probe + repack indices to int32
    k_detect<<<1, 256>>>((const int*)ei);
    k_repack_ei<<<(2 * N_EDGES + 255) / 256, 256>>>(ei);
    k_repack_batch<<<(N_NODES + 255) / 256, 256>>>(batch);

    k_zero_sums<<<(NUM_GRAPHS * HID + 511) / 512, 512>>>();
    k_fuse_head<<<9, 256>>>(Wp1, bp1, Wp2, bp2);

    // layer 0
    k_copy_x_to_agg<<<copy_blocks, 256>>>(reinterpret_cast<const float4*>(x));
    k_scatter<false><<<scatter_blocks, 256>>>(x);
    k_mlp<0><<<mlp_blocks, 128>>>(W1a, b1a, W2a, b2a, nullptr);

    // layer 1 (g_agg already seeded with relu(h0) by k_mlp<0>)
    k_scatter<true><<<scatter_blocks, 256>>>(x);
    k_mlp<1><<<mlp_blocks, 128>>>(W1b, b1b, W2b, b2b, emb_out);

    // head
    k_final<<<(NUM_GRAPHS + 127) / 128, 128>>>(lsm_out);
}

// round 4
// speedup vs baseline: 2.9144x; 1.0819x over previous
#include <cuda_runtime.h>
#include <math.h>

#define N_NODES   100000
#define N_EDGES   1000000
#define HID       64
#define OUT_DIM   32
#define NUM_GRAPHS 512

// ---------------- device scratch -------------------------------------------
__device__ float g_agg[N_NODES * HID];
__device__ float g_h[N_NODES * HID];
__device__ float g_sums[NUM_GRAPHS * HID];
__device__ float g_Wc[HID * OUT_DIM];
__device__ float g_bc[OUT_DIM];
__device__ int   g_is64;
__device__ int   g_ei[2 * N_EDGES];
__device__ int   g_batch[N_NODES];

// ---------------- packed f32x2 helpers --------------------------------------
__device__ __forceinline__ void fma2(unsigned long long& d, unsigned long long a,
                                     unsigned long long b) {
    asm("fma.rn.f32x2 %0, %1, %2, %0;" : "+l"(d) : "l"(a), "l"(b));
}
__device__ __forceinline__ float2 unpack2(unsigned long long v) {
    float lo, hi;
    asm("mov.b64 {%0,%1}, %2;" : "=f"(lo), "=f"(hi) : "l"(v));
    return make_float2(lo, hi);
}
__device__ __forceinline__ unsigned long long pack2(float lo, float hi) {
    unsigned long long r;
    asm("mov.b64 %0, {%1,%2};" : "=l"(r) : "f"(lo), "f"(hi));
    return r;
}
__device__ __forceinline__ void red_add_v4(float* addr, float a, float b, float c, float d) {
    asm volatile("red.global.add.v4.f32 [%0], {%1,%2,%3,%4};"
                 :: "l"(addr), "f"(a), "f"(b), "f"(c), "f"(d) : "memory");
}
__device__ __forceinline__ void red_add_f32(float* addr, float v) {
    asm volatile("red.global.add.f32 [%0], %1;" :: "l"(addr), "f"(v) : "memory");
}

// ---------------- dtype probe + repack --------------------------------------
__global__ void k_detect(const int* __restrict__ ei32) {
    __shared__ int nz;
    if (threadIdx.x == 0) nz = 0;
    __syncthreads();
    if (ei32[2 * threadIdx.x + 1] != 0) nz = 1;   // benign race
    __syncthreads();
    if (threadIdx.x == 0) g_is64 = (nz == 0) ? 1 : 0;
}

__global__ void k_repack(const void* __restrict__ eiv, const void* __restrict__ bv) {
    int i = blockIdx.x * blockDim.x + threadIdx.x;
    int is64 = g_is64;
    if (i < 2 * N_EDGES) {
        g_ei[i] = is64 ? (int)((const long long*)eiv)[i] : ((const int*)eiv)[i];
    } else {
        int j = i - 2 * N_EDGES;
        if (j < N_NODES)
            g_batch[j] = is64 ? (int)((const long long*)bv)[j] : ((const int*)bv)[j];
    }
}

// ---------------- setup: zero sums + fuse head weights ----------------------
__global__ void k_setup(const float* __restrict__ Wp1, const float* __restrict__ bp1,
                        const float* __restrict__ Wp2, const float* __restrict__ bp2) {
    int i = blockIdx.x * blockDim.x + threadIdx.x;
    if (i < NUM_GRAPHS * HID) {
        g_sums[i] = 0.0f;
    } else if (i < NUM_GRAPHS * HID + HID * OUT_DIM) {
        int q = i - NUM_GRAPHS * HID;
        int k = q >> 5, c = q & 31;
        float s = 0.0f;
        for (int m = 0; m < HID; m++) s += Wp1[k * HID + m] * Wp2[m * OUT_DIM + c];
        g_Wc[q] = s;
    } else if (i < NUM_GRAPHS * HID + HID * OUT_DIM + OUT_DIM) {
        int c = i - NUM_GRAPHS * HID - HID * OUT_DIM;
        float s = bp2[c];
        for (int m = 0; m < HID; m++) s += bp1[m] * Wp2[m * OUT_DIM + c];
        g_bc[c] = s;
    }
}

__global__ void k_copy_x_to_agg(const float4* __restrict__ src) {
    int i = blockIdx.x * blockDim.x + threadIdx.x;
    const int n4 = N_NODES * HID / 4;
    if (i < n4) reinterpret_cast<float4*>(g_agg)[i] = src[i];
}

// ---------------- edge scatter: agg[dst] += src_feat[src] -------------------
template <bool USE_H>
__global__ void k_scatter(const float* __restrict__ x) {
    int idx = blockIdx.x * blockDim.x + threadIdx.x;
    if (idx >= N_EDGES * 16) return;
    int e = idx >> 4;
    int c = idx & 15;
    const float* src_feat = USE_H ? g_h : x;
    int s = g_ei[e];
    int d = g_ei[N_EDGES + e];
    float4 v = __ldg(reinterpret_cast<const float4*>(src_feat + (size_t)s * HID) + c);
    red_add_v4(g_agg + (size_t)d * HID + c * 4, v.x, v.y, v.z, v.w);
}

// ---------------- fused GIN MLP with packed f32x2 FMA -----------------------
// 128 threads, 64-node x 64-col tile. cg = t&15, ng = t>>4.
// Thread covers rows ng*8..ng*8+7, cols {cg, cg+16, cg+32, cg+48}.
// acc2[r][j] packs partial sums over even/odd k.
// MODE 0: relu -> g_h and g_agg.  MODE 1: raw -> emb_out, relu red -> g_sums.
template <int MODE>
__global__ void __launch_bounds__(128) k_mlp(
    const float* __restrict__ W1, const float* __restrict__ b1,
    const float* __restrict__ W2, const float* __restrict__ b2,
    float* __restrict__ emb_out)
{
    __shared__ __align__(16) float A[64 * 66];                 // act tile (row-major, pad 66)
    __shared__ __align__(16) unsigned long long WT[64 * 33];   // WT[c][k2] = (W[2k2][c],W[2k2+1][c])
    const int t = threadIdx.x;
    const int base = blockIdx.x * 64;
    const int cg = t & 15;
    const int ng = t >> 4;

    // stage A: 64 rows of g_agg (coalesced float4)
    #pragma unroll
    for (int it = 0; it < 8; it++) {
        int L4 = t + 128 * it;
        int row = L4 >> 4, c4 = L4 & 15;
        int node = base + row;
        float4 v = make_float4(0.f, 0.f, 0.f, 0.f);
        if (node < N_NODES)
            v = __ldg(reinterpret_cast<const float4*>(g_agg + (size_t)node * HID) + c4);
        float* p = A + row * 66 + c4 * 4;
        p[0] = v.x; p[1] = v.y; p[2] = v.z; p[3] = v.w;
    }
    // stage W1 transposed + packed: 2048 pairs, 16 per thread
    #pragma unroll
    for (int it = 0; it < 16; it++) {
        int idx = t + 128 * it;          // idx = k2*64 + c
        int c = idx & 63, k2 = idx >> 6;
        float w0 = __ldg(W1 + (2 * k2) * HID + c);
        float w1 = __ldg(W1 + (2 * k2 + 1) * HID + c);
        WT[c * 33 + k2] = pack2(w0, w1);
    }
    __syncthreads();

    unsigned long long acc2[8][4];
    #pragma unroll
    for (int r = 0; r < 8; r++)
        #pragma unroll
        for (int j = 0; j < 4; j++) acc2[r][j] = 0ULL;

    // ---- phase 1: A @ W1 ----
    #pragma unroll 4
    for (int k2 = 0; k2 < 32; k2++) {
        unsigned long long w0 = WT[(cg +  0) * 33 + k2];
        unsigned long long w1 = WT[(cg + 16) * 33 + k2];
        unsigned long long w2 = WT[(cg + 32) * 33 + k2];
        unsigned long long w3 = WT[(cg + 48) * 33 + k2];
        #pragma unroll
        for (int r = 0; r < 8; r++) {
            unsigned long long a2 =
                *reinterpret_cast<const unsigned long long*>(A + (ng * 8 + r) * 66 + 2 * k2);
            fma2(acc2[r][0], a2, w0);
            fma2(acc2[r][1], a2, w1);
            fma2(acc2[r][2], a2, w2);
            fma2(acc2[r][3], a2, w3);
        }
    }

    float bias[4];
    #pragma unroll
    for (int j = 0; j < 4; j++) bias[j] = __ldg(b1 + cg + 16 * j);

    __syncthreads();   // all phase-1 reads of A and WT done

    // relu -> A (becomes phase-2 input); restage W2 into WT
    #pragma unroll
    for (int r = 0; r < 8; r++) {
        #pragma unroll
        for (int j = 0; j < 4; j++) {
            float2 p = unpack2(acc2[r][j]);
            A[(ng * 8 + r) * 66 + cg + 16 * j] = fmaxf(p.x + p.y + bias[j], 0.0f);
            acc2[r][j] = 0ULL;
        }
    }
    #pragma unroll
    for (int it = 0; it < 16; it++) {
        int idx = t + 128 * it;
        int c = idx & 63, k2 = idx >> 6;
        float w0 = __ldg(W2 + (2 * k2) * HID + c);
        float w1 = __ldg(W2 + (2 * k2 + 1) * HID + c);
        WT[c * 33 + k2] = pack2(w0, w1);
    }
    __syncthreads();

    // ---- phase 2: H @ W2 ----
    #pragma unroll 4
    for (int k2 = 0; k2 < 32; k2++) {
        unsigned long long w0 = WT[(cg +  0) * 33 + k2];
        unsigned long long w1 = WT[(cg + 16) * 33 + k2];
        unsigned long long w2 = WT[(cg + 32) * 33 + k2];
        unsigned long long w3 = WT[(cg + 48) * 33 + k2];
        #pragma unroll
        for (int r = 0; r < 8; r++) {
            unsigned long long a2 =
                *reinterpret_cast<const unsigned long long*>(A + (ng * 8 + r) * 66 + 2 * k2);
            fma2(acc2[r][0], a2, w0);
            fma2(acc2[r][1], a2, w1);
            fma2(acc2[r][2], a2, w2);
            fma2(acc2[r][3], a2, w3);
        }
    }

    #pragma unroll
    for (int j = 0; j < 4; j++) bias[j] = __ldg(b2 + cg + 16 * j);

    // ---- epilogue ----
    #pragma unroll
    for (int r = 0; r < 8; r++) {
        int node = base + ng * 8 + r;
        if (node >= N_NODES) continue;
        if (MODE == 0) {
            #pragma unroll
            for (int j = 0; j < 4; j++) {
                float2 p = unpack2(acc2[r][j]);
                float v = fmaxf(p.x + p.y + bias[j], 0.0f);
                int col = cg + 16 * j;
                g_h  [(size_t)node * HID + col] = v;
                g_agg[(size_t)node * HID + col] = v;
            }
        } else {
            int gidx = g_batch[node];
            #pragma unroll
            for (int j = 0; j < 4; j++) {
                float2 p = unpack2(acc2[r][j]);
                float v = p.x + p.y + bias[j];
                int col = cg + 16 * j;
                emb_out[(size_t)node * HID + col] = v;
                red_add_f32(g_sums + (size_t)gidx * HID + col, fmaxf(v, 0.0f));
            }
        }
    }
}

// ---------------- final head ------------------------------------------------
__global__ void k_final(float* __restrict__ outp) {
    int g = blockIdx.x * blockDim.x + threadIdx.x;
    if (g >= NUM_GRAPHS) return;
    int l0, l1;
    {
        int v = g;
        int a = 0, b = N_NODES;
        while (a < b) { int m = (a + b) >> 1; if (g_batch[m] < v) a = m + 1; else b = m; }
        l0 = a;
        v = g + 1; a = l0; b = N_NODES;
        while (a < b) { int m = (a + b) >> 1; if (g_batch[m] < v) a = m + 1; else b = m; }
        l1 = a;
    }
    float cnt = (float)(l1 - l0);
    float inv = 1.0f / fmaxf(cnt, 1.0f);

    float acc[OUT_DIM];
    #pragma unroll
    for (int c = 0; c < OUT_DIM; c++) acc[c] = g_bc[c];
    for (int k = 0; k < HID; k++) {
        float p = g_sums[g * HID + k] * inv;
        #pragma unroll
        for (int c = 0; c < OUT_DIM; c++) acc[c] += p * g_Wc[k * OUT_DIM + c];
    }
    float m = acc[0];
    #pragma unroll
    for (int c = 1; c < OUT_DIM; c++) m = fmaxf(m, acc[c]);
    float s = 0.0f;
    #pragma unroll
    for (int c = 0; c < OUT_DIM; c++) s += expf(acc[c] - m);
    float ls = logf(s) + m;
    #pragma unroll
    for (int c = 0; c < OUT_DIM; c++) outp[g * OUT_DIM + c] = acc[c] - ls;
}

// ---------------- host launch ------------------------------------------------
extern "C" void kernel_launch(void* const* d_in, const int* in_sizes, int n_in,
                              void* d_out, int out_size) {
    const float* x     = (const float*)d_in[0];
    const void*  ei    = d_in[1];
    const void*  batch = d_in[2];
    const float* W1a = (const float*)d_in[3];
    const float* b1a = (const float*)d_in[4];
    const float* W2a = (const float*)d_in[5];
    const float* b2a = (const float*)d_in[6];
    const float* W1b = (const float*)d_in[7];
    const float* b1b = (const float*)d_in[8];
    const float* W2b = (const float*)d_in[9];
    const float* b2b = (const float*)d_in[10];
    const float* Wp1 = (const float*)d_in[11];
    const float* bp1 = (const float*)d_in[12];
    const float* Wp2 = (const float*)d_in[13];
    const float* bp2 = (const float*)d_in[14];

    float* out     = (float*)d_out;
    float* emb_out = out;
    float* lsm_out = out + (size_t)N_NODES * HID;

    const int mlp_blocks     = (N_NODES + 63) / 64;
    const int copy_blocks    = (N_NODES * HID / 4 + 255) / 256;
    const int scatter_blocks = (N_EDGES * 16 + 255) / 256;
    const int repack_n       = 2 * N_EDGES + N_NODES;
    const int setup_n        = NUM_GRAPHS * HID + HID * OUT_DIM + OUT_DIM;

    k_detect<<<1, 256>>>((const int*)ei);
    k_repack<<<(repack_n + 255) / 256, 256>>>(ei, batch);
    k_setup<<<(setup_n + 255) / 256, 256>>>(Wp1, bp1, Wp2, bp2);

    // layer 0
    k_copy_x_to_agg<<<copy_blocks, 256>>>(reinterpret_cast<const float4*>(x));
    k_scatter<false><<<scatter_blocks, 256>>>(x);
    k_mlp<0><<<mlp_blocks, 128>>>(W1a, b1a, W2a, b2a, nullptr);

    // layer 1
    k_scatter<true><<<scatter_blocks, 256>>>(x);
    k_mlp<1><<<mlp_blocks, 128>>>(W1b, b1b, W2b, b2b, emb_out);

    k_final<<<(NUM_GRAPHS + 127) / 128, 128>>>(lsm_out);
}